// round 16
// baseline (speedup 1.0000x reference)
#include <cuda_runtime.h>
#include <cuda_bf16.h>
#include <cuda_fp16.h>
#include <math.h>
#include <cstdint>

// Problem constants
#define NN 50000
#define EE 300000
#define CC 256            // K*D_OUT
#define NC (NN*CC)        // 12,800,000
#define KH 8
#define N8 (NN*KH)
#define SLOPE 0.2f

// ---------------- scratch (static device allocations) ----------------
__device__ __half g_Hh[4*NC];     // node projections, packed fp16 (gather payload)
__device__ __half g_NRh[4*NC];    // (1-alpha)*(feats[r]@Wres + bres), fp16 payload
__device__ float g_EL[4*N8];      // fp32 logit parts (precision-critical)
__device__ float g_ER[4*N8];
__device__ float g_ATTN[4*512];
__device__ __nv_bfloat16 g_WTH[4*512*256];  // transposed [z][n][k] split-bf16 hi
__device__ __nv_bfloat16 g_WTL[4*512*256];  // lo
__device__ float g_ALPHA[2];

// CSR
__device__ int g_DEG[4*NN];
__device__ int g_ROWPTR[4*(NN+1)];
__device__ int g_WOFF[4*NN];
__device__ int g_ESRC[4*EE];

__device__ __forceinline__ float leaky(float x) { return x >= 0.f ? x : SLOPE*x; }

__device__ __forceinline__ void mma16(float* c, const unsigned* a, const unsigned* b) {
    asm volatile("mma.sync.aligned.m16n8k16.row.col.f32.bf16.bf16.f32 "
        "{%0,%1,%2,%3}, {%4,%5,%6,%7}, {%8,%9}, {%0,%1,%2,%3};"
        : "+f"(c[0]), "+f"(c[1]), "+f"(c[2]), "+f"(c[3])
        : "r"(a[0]), "r"(a[1]), "r"(a[2]), "r"(a[3]), "r"(b[0]), "r"(b[1]));
}

__device__ __forceinline__ unsigned pack2(__nv_bfloat16 a, __nv_bfloat16 b) {
    return (unsigned)__bfloat16_as_ushort(a) | ((unsigned)__bfloat16_as_ushort(b) << 16);
}

__device__ __forceinline__ uint32_t smem_u32(const void* p) {
    uint32_t a;
    asm("{ .reg .u64 t; cvta.to.shared.u64 t, %1; cvt.u32.u64 %0, t; }" : "=r"(a) : "l"(p));
    return a;
}

__device__ __forceinline__ void ldsm_x4(unsigned* r, uint32_t addr) {
    asm volatile("ldmatrix.sync.aligned.m8n8.x4.shared.b16 {%0,%1,%2,%3}, [%4];"
        : "=r"(r[0]), "=r"(r[1]), "=r"(r[2]), "=r"(r[3]) : "r"(addr));
}
__device__ __forceinline__ void ldsm_x2(unsigned* r, uint32_t addr) {
    asm volatile("ldmatrix.sync.aligned.m8n8.x2.shared.b16 {%0,%1}, [%2];"
        : "=r"(r[0]), "=r"(r[1]) : "r"(addr));
}

#define CP_ASYNC16(dst, src) \
    asm volatile("cp.async.ca.shared.global [%0], [%1], 16;" :: "r"(dst), "l"(src) : "memory")
#define CP_COMMIT() asm volatile("cp.async.commit_group;" ::: "memory")
#define CP_WAIT0()  asm volatile("cp.async.wait_group 0;" ::: "memory")

// ---------------- merged setup kernel (attn, relout, alpha, deg-zero, wsplit) ----------------
#define ZB ((4*NN + 511)/512)          // 391 deg-zero blocks
#define WB 1024                        // wsplit blocks (524288 / 512)
__global__ __launch_bounds__(512) void k_setup(const float* __restrict__ rf,
                                               const float* __restrict__ Wr,
                                               const float* __restrict__ Wupd,
                                               const float* __restrict__ bupd,
                                               const float* __restrict__ resw,
                                               const float* __restrict__ W_node,
                                               const float* __restrict__ Wres,
                                               float* __restrict__ out) {
    int b = blockIdx.x;
    int t = threadIdx.x;
    if (b < 4) {
        int r = b;
        float acc = 0.f;
        #pragma unroll 8
        for (int d = 0; d < 64; d++) acc += rf[r*64 + d] * Wr[(r*64 + d)*512 + t];
        g_ATTN[r*512 + t] = acc;
    } else if (b < 8) {
        if (t < 256) {
            int r = b - 4;
            float acc = bupd[r*256 + t];
            #pragma unroll 8
            for (int d = 0; d < 64; d++) acc += rf[r*64 + d] * Wupd[(r*64 + d)*256 + t];
            out[(size_t)4*NC + r*256 + t] = acc;
        }
    } else if (b == 8) {
        if (t < 2) g_ALPHA[t] = 1.0f / (1.0f + expf(-resw[t]));
    } else if (b < 9 + ZB) {
        int i = (b - 9) * 512 + t;
        if (i < 4*NN) g_DEG[i] = 0;
    } else {
        int idx = (b - 9 - ZB) * 512 + t;     // 4*512*256 = 524288
        int z = idx >> 17;
        int rem = idx & 131071;
        int k = rem >> 9;
        int n = rem & 511;
        int dt = 1 - (z & 1);
        float v = (n < 256) ? W_node[dt*65536 + k*256 + n]
                            : Wres[dt*65536 + k*256 + (n - 256)];
        __nv_bfloat16 hi = __float2bfloat16(v);
        __nv_bfloat16 lo = __float2bfloat16(v - __bfloat162float(hi));
        size_t o = (size_t)z*131072 + (size_t)n*256 + k;
        g_WTH[o] = hi;
        g_WTL[o] = lo;
    }
}

// ---------------- CSR build ----------------
__global__ void k_hist(const int* __restrict__ d0, const int* __restrict__ d1,
                       const int* __restrict__ d2, const int* __restrict__ d3) {
    int i = blockIdx.x * 256 + threadIdx.x;
    if (i >= EE) return;
    int r = blockIdx.y;
    const int* dp = r==0?d0:(r==1?d1:(r==2?d2:d3));
    atomicAdd(&g_DEG[r*NN + dp[i]], 1);
}

__global__ __launch_bounds__(1024) void k_scan() {
    int r = blockIdx.x;
    __shared__ int wsum[32];
    __shared__ int carry;
    int tid = threadIdx.x, lane = tid & 31, wid = tid >> 5;
    if (tid == 0) carry = 0;
    __syncthreads();
    for (int base = 0; base < NN; base += 1024) {
        int i = base + tid;
        int v = (i < NN) ? g_DEG[r*NN + i] : 0;
        int x = v;
        #pragma unroll
        for (int off = 1; off < 32; off <<= 1) {
            int t = __shfl_up_sync(0xffffffffu, x, off);
            if (lane >= off) x += t;
        }
        if (lane == 31) wsum[wid] = x;
        __syncthreads();
        if (wid == 0) {
            int y = wsum[lane];
            #pragma unroll
            for (int off = 1; off < 32; off <<= 1) {
                int t = __shfl_up_sync(0xffffffffu, y, off);
                if (lane >= off) y += t;
            }
            wsum[lane] = y;
        }
        __syncthreads();
        int cbase = carry;
        int woff = (wid == 0) ? 0 : wsum[wid - 1];
        int incl = cbase + woff + x;
        if (i < NN) {
            g_ROWPTR[r*(NN+1) + i + 1] = incl;
            g_WOFF[r*NN + i] = incl - v;
        }
        __syncthreads();
        if (tid == 0) carry = cbase + wsum[31];
        __syncthreads();
    }
    if (tid == 0) g_ROWPTR[r*(NN+1)] = 0;
}

__global__ void k_scatter(const int* __restrict__ s0, const int* __restrict__ s1,
                          const int* __restrict__ s2, const int* __restrict__ s3,
                          const int* __restrict__ d0, const int* __restrict__ d1,
                          const int* __restrict__ d2, const int* __restrict__ d3) {
    int i = blockIdx.x * 256 + threadIdx.x;
    if (i >= EE) return;
    int r = blockIdx.y;
    const int* sp = r==0?s0:(r==1?s1:(r==2?s2:s3));
    const int* dp = r==0?d0:(r==1?d1:(r==2?d2:d3));
    int pos = atomicAdd(&g_WOFF[r*NN + dp[i]], 1);
    g_ESRC[r*EE + pos] = sp[i];
}

// ---------------- tensor-core GEMM (3-term split-bf16) + fused el/er epilogue ----------------
#define GBM 128
#define GBN 128
#define APW 12
#define BPW 12
#define APLANE (128*APW)
#define BPLANE (128*BPW)
#define GSMEM_WORDS (4*APLANE + 4*BPLANE)
#define GSMEM_BYTES (GSMEM_WORDS*4)

__global__ __launch_bounds__(256, 2) void k_gemm_bf16(const float* __restrict__ feats,
                                                      const float* __restrict__ bres) {
    extern __shared__ unsigned smw[];
    unsigned* As = smw;
    unsigned* Bs = smw + 4*APLANE;

    int z = blockIdx.z;
    const float* A = feats + (size_t)z * NC;
    const __nv_bfloat16* BTh = g_WTH + (size_t)z * 131072;
    const __nv_bfloat16* BTl = g_WTL + (size_t)z * 131072;
    int row0 = blockIdx.y * GBM;
    int col0 = blockIdx.x * GBN;
    int t = threadIdx.x;
    int lane = t & 31, wid = t >> 5;
    int wm = (wid & 1) * 64;
    int wn = (wid >> 1) * 32;

    uint32_t a_u32 = smem_u32(As);
    uint32_t b_u32 = smem_u32(Bs);

    int a_row_in = (lane & 7) + ((lane >> 3) & 1) * 8;
    int a_sec = lane >> 4;
    int b_row_in = lane & 7;
    int b_sec = (lane >> 3) & 1;

    float4 av[2];
    int am[2], aksw[2];
    #pragma unroll
    for (int i = 0; i < 2; i++) {
        int idx = t + i*256;
        am[i] = idx >> 2;
        aksw[i] = (idx & 3) * 2;
    }
    int bn = t >> 1, bhalf = t & 1;

    float c[4][4][4];
    #pragma unroll
    for (int mi = 0; mi < 4; mi++)
        #pragma unroll
        for (int ni = 0; ni < 4; ni++)
            #pragma unroll
            for (int q = 0; q < 4; q++) c[mi][ni][q] = 0.f;

    auto loadA = [&](int k0) {
        #pragma unroll
        for (int i = 0; i < 2; i++) {
            int gr = row0 + am[i];
            av[i] = (gr < NN) ? *(const float4*)(A + (size_t)gr*256 + k0 + aksw[i]*2)
                              : make_float4(0.f,0.f,0.f,0.f);
        }
    };
    auto cpB = [&](int k0, int buf) {
        size_t bo = ((size_t)(col0 + bn))*256 + k0 + bhalf*8;
        uint32_t dst = b_u32 + (uint32_t)(buf*2*BPLANE + bn*BPW + bhalf*4)*4;
        CP_ASYNC16(dst, (const void*)(BTh + bo));
        CP_ASYNC16(dst + (uint32_t)BPLANE*4, (const void*)(BTl + bo));
    };
    auto storeA = [&](int buf) {
        unsigned* ab = As + buf*2*APLANE;
        #pragma unroll
        for (int i = 0; i < 2; i++) {
            float4 v = av[i];
            __nv_bfloat16 hx = __float2bfloat16(v.x);
            __nv_bfloat16 hy = __float2bfloat16(v.y);
            __nv_bfloat16 hz = __float2bfloat16(v.z);
            __nv_bfloat16 hw = __float2bfloat16(v.w);
            unsigned hi0 = pack2(hx, hy), hi1 = pack2(hz, hw);
            unsigned lo0 = pack2(__float2bfloat16(v.x - __bfloat162float(hx)),
                                 __float2bfloat16(v.y - __bfloat162float(hy)));
            unsigned lo1 = pack2(__float2bfloat16(v.z - __bfloat162float(hz)),
                                 __float2bfloat16(v.w - __bfloat162float(hw)));
            int w = am[i]*APW + aksw[i];
            *(uint2*)(ab + w) = make_uint2(hi0, hi1);
            *(uint2*)(ab + APLANE + w) = make_uint2(lo0, lo1);
        }
    };

    loadA(0);
    cpB(0, 0);
    CP_COMMIT();
    storeA(0);
    CP_WAIT0();
    __syncthreads();

    #pragma unroll 1
    for (int kt = 0; kt < 16; kt++) {
        if (kt + 1 < 16) {
            loadA((kt + 1) * 16);
            cpB((kt + 1) * 16, (kt + 1) & 1);
            CP_COMMIT();
        }
        int buf = kt & 1;
        uint32_t aB = a_u32 + (uint32_t)(buf*2*APLANE)*4;
        uint32_t bB = b_u32 + (uint32_t)(buf*2*BPLANE)*4;

        unsigned af[4][2][4];
        #pragma unroll
        for (int mi = 0; mi < 4; mi++) {
            uint32_t addr = aB + (uint32_t)((wm + mi*16 + a_row_in)*APW)*4 + a_sec*16;
            ldsm_x4(af[mi][0], addr);
            ldsm_x4(af[mi][1], addr + (uint32_t)APLANE*4);
        }
        unsigned bfr[4][2][2];
        #pragma unroll
        for (int ni = 0; ni < 4; ni++) {
            uint32_t addr = bB + (uint32_t)((wn + ni*8 + b_row_in)*BPW)*4 + b_sec*16;
            ldsm_x2(bfr[ni][0], addr);
            ldsm_x2(bfr[ni][1], addr + (uint32_t)BPLANE*4);
        }
        #pragma unroll
        for (int mi = 0; mi < 4; mi++)
            #pragma unroll
            for (int ni = 0; ni < 4; ni++) {
                mma16(c[mi][ni], af[mi][0], bfr[ni][0]);
                mma16(c[mi][ni], af[mi][0], bfr[ni][1]);
                mma16(c[mi][ni], af[mi][1], bfr[ni][0]);
            }
        if (kt + 1 < 16) storeA((kt + 1) & 1);
        CP_WAIT0();
        __syncthreads();
    }

    int lr = lane >> 2;
    int lc = lane & 3;
    int dt = 1 - (z & 1);
    float om = 1.0f - g_ALPHA[dt];
    bool isH = (col0 < 256);

    if (isH) {
        const int REV4[4] = {1, 0, 3, 2};
        int rz = REV4[z];
        int hd = (col0 + wn) >> 5;
        float aLv[8], aRv[8];
        #pragma unroll
        for (int ni = 0; ni < 4; ni++) {
            #pragma unroll
            for (int q = 0; q < 2; q++) {
                int d = ni*8 + 2*lc + q;
                aLv[ni*2+q] = g_ATTN[rz*512 + hd*64 + d];
                aRv[ni*2+q] = g_ATTN[z*512 + hd*64 + 32 + d];
            }
        }
        #pragma unroll
        for (int mi = 0; mi < 4; mi++) {
            int r0 = row0 + wm + mi*16 + lr;
            float el0 = 0.f, er0 = 0.f, el8 = 0.f, er8 = 0.f;
            #pragma unroll
            for (int ni = 0; ni < 4; ni++) {
                int col = col0 + wn + ni*8 + 2*lc;
                float v0 = c[mi][ni][0], v1 = c[mi][ni][1];
                float v2 = c[mi][ni][2], v3 = c[mi][ni][3];
                el0 += v0*aLv[ni*2] + v1*aLv[ni*2+1];
                er0 += v0*aRv[ni*2] + v1*aRv[ni*2+1];
                el8 += v2*aLv[ni*2] + v3*aLv[ni*2+1];
                er8 += v2*aRv[ni*2] + v3*aRv[ni*2+1];
                if (r0 < NN)
                    *(__half2*)(g_Hh + (size_t)z*NC + (size_t)r0*256 + col) =
                        __floats2half2_rn(v0, v1);
                if (r0 + 8 < NN)
                    *(__half2*)(g_Hh + (size_t)z*NC + (size_t)(r0+8)*256 + col) =
                        __floats2half2_rn(v2, v3);
            }
            el0 += __shfl_xor_sync(0xffffffffu, el0, 1);
            el0 += __shfl_xor_sync(0xffffffffu, el0, 2);
            er0 += __shfl_xor_sync(0xffffffffu, er0, 1);
            er0 += __shfl_xor_sync(0xffffffffu, er0, 2);
            el8 += __shfl_xor_sync(0xffffffffu, el8, 1);
            el8 += __shfl_xor_sync(0xffffffffu, el8, 2);
            er8 += __shfl_xor_sync(0xffffffffu, er8, 1);
            er8 += __shfl_xor_sync(0xffffffffu, er8, 2);
            if (lc == 0) {
                if (r0 < NN) {
                    g_EL[rz*N8 + r0*KH + hd] = el0;
                    g_ER[z*N8 + r0*KH + hd] = er0;
                }
                if (r0 + 8 < NN) {
                    g_EL[rz*N8 + (r0+8)*KH + hd] = el8;
                    g_ER[z*N8 + (r0+8)*KH + hd] = er8;
                }
            }
        }
    } else {
        #pragma unroll
        for (int mi = 0; mi < 4; mi++) {
            int r0 = row0 + wm + mi*16 + lr;
            #pragma unroll
            for (int ni = 0; ni < 4; ni++) {
                int col = col0 + wn + ni*8 + 2*lc;
                int c2 = col - 256;
                float b0 = bres[dt*256 + c2], b1 = bres[dt*256 + c2 + 1];
                if (r0 < NN)
                    *(__half2*)(g_NRh + (size_t)z*NC + (size_t)r0*256 + c2) =
                        __floats2half2_rn(om*(c[mi][ni][0] + b0), om*(c[mi][ni][1] + b1));
                if (r0 + 8 < NN)
                    *(__half2*)(g_NRh + (size_t)z*NC + (size_t)(r0+8)*256 + c2) =
                        __floats2half2_rn(om*(c[mi][ni][2] + b0), om*(c[mi][ni][3] + b1));
            }
        }
    }
}

// ---------------- fused conv + residual + cross-relation attention ----------------
// Single-pass softmax; H and NR gathered in fp16 (logits stay fp32 via g_EL/g_ER).
__global__ __launch_bounds__(256) void k_convcross(const float* __restrict__ rel_attn,
                                                   float* __restrict__ out) {
    __shared__ float sh[4][2][256];
    int g = blockIdx.y;
    int warp = threadIdx.x >> 5;
    int lane = threadIdx.x & 31;
    int nloc = warp >> 1;
    int q = warp & 1;
    int n = blockIdx.x * 4 + nloc;
    const int REV[4] = {1, 0, 3, 2};
    int rel0 = (g == 0) ? 0 : 1;
    int rel1 = (g == 0) ? 2 : 3;
    int r = q ? rel1 : rel0;
    int dt = 1 - g;
    float alpha = g_ALPHA[dt];
    bool valid = (n < NN);

    if (valid) {
        int start = g_ROWPTR[r*(NN+1) + n];
        int end   = g_ROWPTR[r*(NN+1) + n + 1];
        float acc[8] = {0.f,0.f,0.f,0.f,0.f,0.f,0.f,0.f};
        if (start < end) {
            const int* esrc = g_ESRC + r*EE;
            const float* EL = g_EL + r*N8;
            int k2 = lane >> 2;
            float er2 = g_ER[r*N8 + n*KH + k2];
            const __half* Hp = g_Hh + (size_t)REV[r]*NC;
            float z = 0.f;

            int j = start;
            for (; j + 1 < end; j += 2) {
                int s0 = esrc[j], s1 = esrc[j+1];
                float w0 = __expf(leaky(EL[s0*KH + k2] + er2));
                float w1 = __expf(leaky(EL[s1*KH + k2] + er2));
                z += w0 + w1;
                uint4 ha = *(const uint4*)(Hp + (size_t)s0*256 + lane*8);
                uint4 hb = *(const uint4*)(Hp + (size_t)s1*256 + lane*8);
                float2 a0 = __half22float2(*(__half2*)&ha.x);
                float2 a1 = __half22float2(*(__half2*)&ha.y);
                float2 a2 = __half22float2(*(__half2*)&ha.z);
                float2 a3 = __half22float2(*(__half2*)&ha.w);
                float2 b0 = __half22float2(*(__half2*)&hb.x);
                float2 b1 = __half22float2(*(__half2*)&hb.y);
                float2 b2 = __half22float2(*(__half2*)&hb.z);
                float2 b3 = __half22float2(*(__half2*)&hb.w);
                acc[0] += w0*a0.x + w1*b0.x; acc[1] += w0*a0.y + w1*b0.y;
                acc[2] += w0*a1.x + w1*b1.x; acc[3] += w0*a1.y + w1*b1.y;
                acc[4] += w0*a2.x + w1*b2.x; acc[5] += w0*a2.y + w1*b2.y;
                acc[6] += w0*a3.x + w1*b3.x; acc[7] += w0*a3.y + w1*b3.y;
            }
            if (j < end) {
                int s0 = esrc[j];
                float w0 = __expf(leaky(EL[s0*KH + k2] + er2));
                z += w0;
                uint4 ha = *(const uint4*)(Hp + (size_t)s0*256 + lane*8);
                float2 a0 = __half22float2(*(__half2*)&ha.x);
                float2 a1 = __half22float2(*(__half2*)&ha.y);
                float2 a2 = __half22float2(*(__half2*)&ha.z);
                float2 a3 = __half22float2(*(__half2*)&ha.w);
                acc[0] += w0*a0.x; acc[1] += w0*a0.y;
                acc[2] += w0*a1.x; acc[3] += w0*a1.y;
                acc[4] += w0*a2.x; acc[5] += w0*a2.y;
                acc[6] += w0*a3.x; acc[7] += w0*a3.y;
            }
            float rz = 1.0f / z;
            #pragma unroll
            for (int e = 0; e < 8; e++) acc[e] *= rz;
        }
        uint4 nr = *(const uint4*)(g_NRh + (size_t)r*NC + (size_t)n*256 + lane*8);
        float2 i0 = __half22float2(*(__half2*)&nr.x);
        float2 i1 = __half22float2(*(__half2*)&nr.y);
        float2 i2 = __half22float2(*(__half2*)&nr.z);
        float2 i3 = __half22float2(*(__half2*)&nr.w);
        float* sp = &sh[nloc][q][lane*8];
        sp[0] = alpha*fmaxf(acc[0],0.f) + i0.x;
        sp[1] = alpha*fmaxf(acc[1],0.f) + i0.y;
        sp[2] = alpha*fmaxf(acc[2],0.f) + i1.x;
        sp[3] = alpha*fmaxf(acc[3],0.f) + i1.y;
        sp[4] = alpha*fmaxf(acc[4],0.f) + i2.x;
        sp[5] = alpha*fmaxf(acc[5],0.f) + i2.y;
        sp[6] = alpha*fmaxf(acc[6],0.f) + i3.x;
        sp[7] = alpha*fmaxf(acc[7],0.f) + i3.y;
    }
    __syncthreads();
    if (!valid) return;

    float h0[8], h1[8];
    {
        const float* p0 = &sh[nloc][0][lane*8];
        const float* p1 = &sh[nloc][1][lane*8];
        float4 a0 = *(const float4*)p0, a1 = *(const float4*)(p0+4);
        float4 b0 = *(const float4*)p1, b1 = *(const float4*)(p1+4);
        h0[0]=a0.x; h0[1]=a0.y; h0[2]=a0.z; h0[3]=a0.w;
        h0[4]=a1.x; h0[5]=a1.y; h0[6]=a1.z; h0[7]=a1.w;
        h1[0]=b0.x; h1[1]=b0.y; h1[2]=b0.z; h1[3]=b0.w;
        h1[4]=b1.x; h1[5]=b1.y; h1[6]=b1.z; h1[7]=b1.w;
    }
    int ro = q ? rel1 : rel0;
    const float* ra = rel_attn + ro*256 + lane*8;
    float s0 = 0.f, s1 = 0.f;
    #pragma unroll
    for (int j = 0; j < 8; j++) { s0 += h0[j]*ra[j]; s1 += h1[j]*ra[j]; }
    s0 += __shfl_xor_sync(0xffffffffu, s0, 1);
    s0 += __shfl_xor_sync(0xffffffffu, s0, 2);
    s1 += __shfl_xor_sync(0xffffffffu, s1, 1);
    s1 += __shfl_xor_sync(0xffffffffu, s1, 2);
    s0 = leaky(s0); s1 = leaky(s1);
    float mx = fmaxf(s0, s1);
    float w0 = __expf(s0 - mx), w1 = __expf(s1 - mx);
    float inv = 1.0f / (w0 + w1);
    w0 *= inv; w1 *= inv;
    float o[8];
    #pragma unroll
    for (int j = 0; j < 8; j++) o[j] = w0*h0[j] + w1*h1[j];
    float* op = out + (size_t)ro*NC + (size_t)n*256 + lane*8;
    *(float4*)op = make_float4(o[0],o[1],o[2],o[3]);
    *(float4*)(op+4) = make_float4(o[4],o[5],o[6],o[7]);
}

// ---------------- launch ----------------
extern "C" void kernel_launch(void* const* d_in, const int* in_sizes, int n_in,
                              void* d_out, int out_size) {
    const float* feats      = (const float*)d_in[0];
    const float* rel_feats  = (const float*)d_in[1];
    const int*   src_rates  = (const int*)d_in[2];
    const int*   dst_rates  = (const int*)d_in[3];
    const int*   src_clicks = (const int*)d_in[4];
    const int*   dst_clicks = (const int*)d_in[5];
    const float* W_node     = (const float*)d_in[6];
    const float* Wr         = (const float*)d_in[7];
    const float* Wres       = (const float*)d_in[8];
    const float* bres       = (const float*)d_in[9];
    const float* resw       = (const float*)d_in[10];
    const float* rel_attn   = (const float*)d_in[11];
    const float* Wupd       = (const float*)d_in[12];
    const float* bupd       = (const float*)d_in[13];
    float* out = (float*)d_out;

    const int* S0 = src_rates;  const int* S1 = dst_rates;
    const int* S2 = src_clicks; const int* S3 = dst_clicks;
    const int* D0 = dst_rates;  const int* D1 = src_rates;
    const int* D2 = dst_clicks; const int* D3 = src_clicks;

    static cudaStream_t s2 = nullptr;
    static cudaEvent_t evFork = nullptr, evJoin = nullptr;
    static int init_done = 0;
    if (!init_done) {
        cudaFuncSetAttribute(k_gemm_bf16, cudaFuncAttributeMaxDynamicSharedMemorySize, GSMEM_BYTES);
        cudaStreamCreateWithFlags(&s2, cudaStreamNonBlocking);
        cudaEventCreateWithFlags(&evFork, cudaEventDisableTiming);
        cudaEventCreateWithFlags(&evJoin, cudaEventDisableTiming);
        init_done = 1;
    }

    int setup_blocks = 9 + ZB + WB;
    k_setup<<<setup_blocks, 512>>>(rel_feats, Wr, Wupd, bupd, resw, W_node, Wres, out);

    // fork: CSR chain on s2, GEMM path on the main stream
    cudaEventRecord(evFork, 0);
    cudaStreamWaitEvent(s2, evFork, 0);
    k_hist<<<dim3((EE + 255)/256, 4), 256, 0, s2>>>(D0, D1, D2, D3);
    k_scan<<<4, 1024, 0, s2>>>();
    k_scatter<<<dim3((EE + 255)/256, 4), 256, 0, s2>>>(S0,S1,S2,S3, D0,D1,D2,D3);
    cudaEventRecord(evJoin, s2);

    dim3 ggrid(512/GBN, (NN + GBM - 1)/GBM, 4);
    k_gemm_bf16<<<ggrid, 256, GSMEM_BYTES>>>(feats, bres);

    // join before the consumer
    cudaStreamWaitEvent(0, evJoin, 0);
    k_convcross<<<dim3((NN + 3)/4, 2), 256>>>(rel_attn, out);
}

// round 17
// speedup vs baseline: 1.2823x; 1.2823x over previous
#include <cuda_runtime.h>
#include <cuda_fp16.h>
#include <math.h>
#include <cstdint>

// Problem constants
#define NN 50000
#define EE 300000
#define CC 256            // K*D_OUT
#define NC (NN*CC)        // 12,800,000
#define KH 8
#define N8 (NN*KH)
#define SLOPE 0.2f

// ---------------- scratch (static device allocations) ----------------
__device__ __half g_Hh[4*NC];     // node projections, packed fp16 (gather payload)
__device__ float g_NR[4*NC];      // (1-alpha)*(feats[r]@Wres + bres) (fp32)
__device__ float g_EL[4*N8];      // fp32 logit parts (precision-critical)
__device__ float g_ER[4*N8];
__device__ float g_ATTN[4*512];
__device__ __half g_WTH[4*512*256];  // transposed [z][n][k] fp16 weights (single plane)
__device__ float g_ALPHA[2];

// CSR
__device__ int g_DEG[4*NN];
__device__ int g_ROWPTR[4*(NN+1)];
__device__ int g_WOFF[4*NN];
__device__ int g_ESRC[4*EE];

__device__ __forceinline__ float leaky(float x) { return x >= 0.f ? x : SLOPE*x; }

// fp16 m16n8k16 mma, fp32 accumulate
__device__ __forceinline__ void mma16h(float* c, const unsigned* a, const unsigned* b) {
    asm volatile("mma.sync.aligned.m16n8k16.row.col.f32.f16.f16.f32 "
        "{%0,%1,%2,%3}, {%4,%5,%6,%7}, {%8,%9}, {%0,%1,%2,%3};"
        : "+f"(c[0]), "+f"(c[1]), "+f"(c[2]), "+f"(c[3])
        : "r"(a[0]), "r"(a[1]), "r"(a[2]), "r"(a[3]), "r"(b[0]), "r"(b[1]));
}

__device__ __forceinline__ unsigned pack2h(__half a, __half b) {
    __half2 h = __halves2half2(a, b);
    return *(unsigned*)&h;
}

__device__ __forceinline__ uint32_t smem_u32(const void* p) {
    uint32_t a;
    asm("{ .reg .u64 t; cvta.to.shared.u64 t, %1; cvt.u32.u64 %0, t; }" : "=r"(a) : "l"(p));
    return a;
}

__device__ __forceinline__ void ldsm_x4(unsigned* r, uint32_t addr) {
    asm volatile("ldmatrix.sync.aligned.m8n8.x4.shared.b16 {%0,%1,%2,%3}, [%4];"
        : "=r"(r[0]), "=r"(r[1]), "=r"(r[2]), "=r"(r[3]) : "r"(addr));
}
__device__ __forceinline__ void ldsm_x2(unsigned* r, uint32_t addr) {
    asm volatile("ldmatrix.sync.aligned.m8n8.x2.shared.b16 {%0,%1}, [%2];"
        : "=r"(r[0]), "=r"(r[1]) : "r"(addr));
}

#define CP_ASYNC16(dst, src) \
    asm volatile("cp.async.ca.shared.global [%0], [%1], 16;" :: "r"(dst), "l"(src) : "memory")
#define CP_COMMIT() asm volatile("cp.async.commit_group;" ::: "memory")
#define CP_WAIT0()  asm volatile("cp.async.wait_group 0;" ::: "memory")

// ---------------- merged setup kernel (attn, relout, alpha, deg-zero) ----------------
__global__ __launch_bounds__(512) void k_setup(const float* __restrict__ rf,
                                               const float* __restrict__ Wr,
                                               const float* __restrict__ Wupd,
                                               const float* __restrict__ bupd,
                                               const float* __restrict__ resw,
                                               float* __restrict__ out) {
    int b = blockIdx.x;
    int t = threadIdx.x;
    if (b < 4) {
        int r = b;
        float acc = 0.f;
        #pragma unroll 8
        for (int d = 0; d < 64; d++) acc += rf[r*64 + d] * Wr[(r*64 + d)*512 + t];
        g_ATTN[r*512 + t] = acc;
    } else if (b < 8) {
        if (t < 256) {
            int r = b - 4;
            float acc = bupd[r*256 + t];
            #pragma unroll 8
            for (int d = 0; d < 64; d++) acc += rf[r*64 + d] * Wupd[(r*64 + d)*256 + t];
            out[(size_t)4*NC + r*256 + t] = acc;
        }
    } else if (b == 8) {
        if (t < 2) g_ALPHA[t] = 1.0f / (1.0f + expf(-resw[t]));
    } else {
        int i = (b - 9) * 512 + t;
        if (i < 4*NN) g_DEG[i] = 0;
    }
}

// fp16 transposed weights: [z][n(512)][k(256)]
__global__ void k_wsplit(const float* __restrict__ W_node, const float* __restrict__ Wres) {
    int idx = blockIdx.x * 256 + threadIdx.x;     // 4*512*256 = 524288
    int z = idx >> 17;
    int rem = idx & 131071;
    int k = rem >> 9;
    int n = rem & 511;
    int dt = 1 - (z & 1);
    float v = (n < 256) ? W_node[dt*65536 + k*256 + n]
                        : Wres[dt*65536 + k*256 + (n - 256)];
    g_WTH[(size_t)z*131072 + (size_t)n*256 + k] = __float2half(v);
}

// ---------------- CSR build ----------------
__global__ void k_hist(const int* __restrict__ d0, const int* __restrict__ d1,
                       const int* __restrict__ d2, const int* __restrict__ d3) {
    int i = blockIdx.x * 256 + threadIdx.x;
    if (i >= EE) return;
    int r = blockIdx.y;
    const int* dp = r==0?d0:(r==1?d1:(r==2?d2:d3));
    atomicAdd(&g_DEG[r*NN + dp[i]], 1);
}

__global__ __launch_bounds__(1024) void k_scan() {
    int r = blockIdx.x;
    __shared__ int wsum[32];
    __shared__ int carry;
    int tid = threadIdx.x, lane = tid & 31, wid = tid >> 5;
    if (tid == 0) carry = 0;
    __syncthreads();
    for (int base = 0; base < NN; base += 1024) {
        int i = base + tid;
        int v = (i < NN) ? g_DEG[r*NN + i] : 0;
        int x = v;
        #pragma unroll
        for (int off = 1; off < 32; off <<= 1) {
            int t = __shfl_up_sync(0xffffffffu, x, off);
            if (lane >= off) x += t;
        }
        if (lane == 31) wsum[wid] = x;
        __syncthreads();
        if (wid == 0) {
            int y = wsum[lane];
            #pragma unroll
            for (int off = 1; off < 32; off <<= 1) {
                int t = __shfl_up_sync(0xffffffffu, y, off);
                if (lane >= off) y += t;
            }
            wsum[lane] = y;
        }
        __syncthreads();
        int cbase = carry;
        int woff = (wid == 0) ? 0 : wsum[wid - 1];
        int incl = cbase + woff + x;
        if (i < NN) {
            g_ROWPTR[r*(NN+1) + i + 1] = incl;
            g_WOFF[r*NN + i] = incl - v;
        }
        __syncthreads();
        if (tid == 0) carry = cbase + wsum[31];
        __syncthreads();
    }
    if (tid == 0) g_ROWPTR[r*(NN+1)] = 0;
}

__global__ void k_scatter(const int* __restrict__ s0, const int* __restrict__ s1,
                          const int* __restrict__ s2, const int* __restrict__ s3,
                          const int* __restrict__ d0, const int* __restrict__ d1,
                          const int* __restrict__ d2, const int* __restrict__ d3) {
    int i = blockIdx.x * 256 + threadIdx.x;
    if (i >= EE) return;
    int r = blockIdx.y;
    const int* sp = r==0?s0:(r==1?s1:(r==2?s2:s3));
    const int* dp = r==0?d0:(r==1?d1:(r==2?d2:d3));
    int pos = atomicAdd(&g_WOFF[r*NN + dp[i]], 1);
    g_ESRC[r*EE + pos] = sp[i];
}

// ---------------- tensor-core GEMM (2-term fp16 split) + fused el/er epilogue ----------------
// D = Ah*Bh + Al*Bh (B single fp16 plane). 32 HMMAs per K-slab iter.
#define GBM 128
#define GBN 128
#define APW 12
#define BPW 12
#define APLANE (128*APW)
#define BPLANE (128*BPW)
#define GSMEM_WORDS (4*APLANE + 2*BPLANE)
#define GSMEM_BYTES (GSMEM_WORDS*4)

__global__ __launch_bounds__(256, 2) void k_gemm_fp16(const float* __restrict__ feats,
                                                      const float* __restrict__ bres) {
    extern __shared__ unsigned smw[];
    unsigned* As = smw;                 // [buf][plane(hi/lo)][APLANE]
    unsigned* Bs = smw + 4*APLANE;      // [buf][BPLANE]

    int z = blockIdx.z;
    const float* A = feats + (size_t)z * NC;
    const __half* BT = g_WTH + (size_t)z * 131072;
    int row0 = blockIdx.y * GBM;
    int col0 = blockIdx.x * GBN;
    int t = threadIdx.x;
    int lane = t & 31, wid = t >> 5;
    int wm = (wid & 1) * 64;
    int wn = (wid >> 1) * 32;

    uint32_t a_u32 = smem_u32(As);
    uint32_t b_u32 = smem_u32(Bs);

    int a_row_in = (lane & 7) + ((lane >> 3) & 1) * 8;
    int a_sec = lane >> 4;
    int b_row_in = lane & 7;
    int b_sec = (lane >> 3) & 1;

    float4 av[2];
    int am[2], aksw[2];
    #pragma unroll
    for (int i = 0; i < 2; i++) {
        int idx = t + i*256;
        am[i] = idx >> 2;
        aksw[i] = (idx & 3) * 2;
    }
    int bn = t >> 1, bhalf = t & 1;

    float c[4][4][4];
    #pragma unroll
    for (int mi = 0; mi < 4; mi++)
        #pragma unroll
        for (int ni = 0; ni < 4; ni++)
            #pragma unroll
            for (int q = 0; q < 4; q++) c[mi][ni][q] = 0.f;

    auto loadA = [&](int k0) {
        #pragma unroll
        for (int i = 0; i < 2; i++) {
            int gr = row0 + am[i];
            av[i] = (gr < NN) ? *(const float4*)(A + (size_t)gr*256 + k0 + aksw[i]*2)
                              : make_float4(0.f,0.f,0.f,0.f);
        }
    };
    auto cpB = [&](int k0, int buf) {
        size_t bo = ((size_t)(col0 + bn))*256 + k0 + bhalf*8;
        uint32_t dst = b_u32 + (uint32_t)(buf*BPLANE + bn*BPW + bhalf*4)*4;
        CP_ASYNC16(dst, (const void*)(BT + bo));
    };
    auto storeA = [&](int buf) {
        unsigned* ab = As + buf*2*APLANE;
        #pragma unroll
        for (int i = 0; i < 2; i++) {
            float4 v = av[i];
            __half hx = __float2half(v.x);
            __half hy = __float2half(v.y);
            __half hz = __float2half(v.z);
            __half hw = __float2half(v.w);
            unsigned hi0 = pack2h(hx, hy), hi1 = pack2h(hz, hw);
            unsigned lo0 = pack2h(__float2half(v.x - __half2float(hx)),
                                  __float2half(v.y - __half2float(hy)));
            unsigned lo1 = pack2h(__float2half(v.z - __half2float(hz)),
                                  __float2half(v.w - __half2float(hw)));
            int w = am[i]*APW + aksw[i];
            *(uint2*)(ab + w) = make_uint2(hi0, hi1);
            *(uint2*)(ab + APLANE + w) = make_uint2(lo0, lo1);
        }
    };

    loadA(0);
    cpB(0, 0);
    CP_COMMIT();
    storeA(0);
    CP_WAIT0();
    __syncthreads();

    #pragma unroll 1
    for (int kt = 0; kt < 16; kt++) {
        if (kt + 1 < 16) {
            loadA((kt + 1) * 16);
            cpB((kt + 1) * 16, (kt + 1) & 1);
            CP_COMMIT();
        }
        int buf = kt & 1;
        uint32_t aB = a_u32 + (uint32_t)(buf*2*APLANE)*4;
        uint32_t bB = b_u32 + (uint32_t)(buf*BPLANE)*4;

        unsigned af[4][2][4];
        #pragma unroll
        for (int mi = 0; mi < 4; mi++) {
            uint32_t addr = aB + (uint32_t)((wm + mi*16 + a_row_in)*APW)*4 + a_sec*16;
            ldsm_x4(af[mi][0], addr);
            ldsm_x4(af[mi][1], addr + (uint32_t)APLANE*4);
        }
        unsigned bfr[4][2];
        #pragma unroll
        for (int ni = 0; ni < 4; ni++) {
            uint32_t addr = bB + (uint32_t)((wn + ni*8 + b_row_in)*BPW)*4 + b_sec*16;
            ldsm_x2(bfr[ni], addr);
        }
        #pragma unroll
        for (int mi = 0; mi < 4; mi++)
            #pragma unroll
            for (int ni = 0; ni < 4; ni++) {
                mma16h(c[mi][ni], af[mi][0], bfr[ni]);   // Ah*Bh
                mma16h(c[mi][ni], af[mi][1], bfr[ni]);   // Al*Bh
            }
        if (kt + 1 < 16) storeA((kt + 1) & 1);
        CP_WAIT0();
        __syncthreads();
    }

    int lr = lane >> 2;
    int lc = lane & 3;
    int dt = 1 - (z & 1);
    float om = 1.0f - g_ALPHA[dt];
    bool isH = (col0 < 256);

    if (isH) {
        const int REV4[4] = {1, 0, 3, 2};
        int rz = REV4[z];
        int hd = (col0 + wn) >> 5;
        float aLv[8], aRv[8];
        #pragma unroll
        for (int ni = 0; ni < 4; ni++) {
            #pragma unroll
            for (int q = 0; q < 2; q++) {
                int d = ni*8 + 2*lc + q;
                aLv[ni*2+q] = g_ATTN[rz*512 + hd*64 + d];
                aRv[ni*2+q] = g_ATTN[z*512 + hd*64 + 32 + d];
            }
        }
        #pragma unroll
        for (int mi = 0; mi < 4; mi++) {
            int r0 = row0 + wm + mi*16 + lr;
            float el0 = 0.f, er0 = 0.f, el8 = 0.f, er8 = 0.f;
            #pragma unroll
            for (int ni = 0; ni < 4; ni++) {
                int col = col0 + wn + ni*8 + 2*lc;
                float v0 = c[mi][ni][0], v1 = c[mi][ni][1];
                float v2 = c[mi][ni][2], v3 = c[mi][ni][3];
                el0 += v0*aLv[ni*2] + v1*aLv[ni*2+1];
                er0 += v0*aRv[ni*2] + v1*aRv[ni*2+1];
                el8 += v2*aLv[ni*2] + v3*aLv[ni*2+1];
                er8 += v2*aRv[ni*2] + v3*aRv[ni*2+1];
                if (r0 < NN)
                    *(__half2*)(g_Hh + (size_t)z*NC + (size_t)r0*256 + col) =
                        __floats2half2_rn(v0, v1);
                if (r0 + 8 < NN)
                    *(__half2*)(g_Hh + (size_t)z*NC + (size_t)(r0+8)*256 + col) =
                        __floats2half2_rn(v2, v3);
            }
            el0 += __shfl_xor_sync(0xffffffffu, el0, 1);
            el0 += __shfl_xor_sync(0xffffffffu, el0, 2);
            er0 += __shfl_xor_sync(0xffffffffu, er0, 1);
            er0 += __shfl_xor_sync(0xffffffffu, er0, 2);
            el8 += __shfl_xor_sync(0xffffffffu, el8, 1);
            el8 += __shfl_xor_sync(0xffffffffu, el8, 2);
            er8 += __shfl_xor_sync(0xffffffffu, er8, 1);
            er8 += __shfl_xor_sync(0xffffffffu, er8, 2);
            if (lc == 0) {
                if (r0 < NN) {
                    g_EL[rz*N8 + r0*KH + hd] = el0;
                    g_ER[z*N8 + r0*KH + hd] = er0;
                }
                if (r0 + 8 < NN) {
                    g_EL[rz*N8 + (r0+8)*KH + hd] = el8;
                    g_ER[z*N8 + (r0+8)*KH + hd] = er8;
                }
            }
        }
    } else {
        #pragma unroll
        for (int mi = 0; mi < 4; mi++) {
            int r0 = row0 + wm + mi*16 + lr;
            #pragma unroll
            for (int ni = 0; ni < 4; ni++) {
                int col = col0 + wn + ni*8 + 2*lc;
                int c2 = col - 256;
                float b0 = bres[dt*256 + c2], b1 = bres[dt*256 + c2 + 1];
                if (r0 < NN)
                    *(float2*)(g_NR + (size_t)z*NC + (size_t)r0*256 + c2) =
                        make_float2(om*(c[mi][ni][0] + b0), om*(c[mi][ni][1] + b1));
                if (r0 + 8 < NN)
                    *(float2*)(g_NR + (size_t)z*NC + (size_t)(r0+8)*256 + c2) =
                        make_float2(om*(c[mi][ni][2] + b0), om*(c[mi][ni][3] + b1));
            }
        }
    }
}

// ---------------- fused conv + residual + cross-relation attention ----------------
// Single-pass softmax; H gathered in fp16 (logits stay fp32 via g_EL/g_ER).
__global__ __launch_bounds__(256) void k_convcross(const float* __restrict__ rel_attn,
                                                   float* __restrict__ out) {
    __shared__ float sh[4][2][256];
    int g = blockIdx.y;
    int warp = threadIdx.x >> 5;
    int lane = threadIdx.x & 31;
    int nloc = warp >> 1;
    int q = warp & 1;
    int n = blockIdx.x * 4 + nloc;
    const int REV[4] = {1, 0, 3, 2};
    int rel0 = (g == 0) ? 0 : 1;
    int rel1 = (g == 0) ? 2 : 3;
    int r = q ? rel1 : rel0;
    int dt = 1 - g;
    float alpha = g_ALPHA[dt];
    bool valid = (n < NN);

    if (valid) {
        int start = g_ROWPTR[r*(NN+1) + n];
        int end   = g_ROWPTR[r*(NN+1) + n + 1];
        float acc[8] = {0.f,0.f,0.f,0.f,0.f,0.f,0.f,0.f};
        if (start < end) {
            const int* esrc = g_ESRC + r*EE;
            const float* EL = g_EL + r*N8;
            int k2 = lane >> 2;
            float er2 = g_ER[r*N8 + n*KH + k2];
            const __half* Hp = g_Hh + (size_t)REV[r]*NC;
            float z = 0.f;

            int j = start;
            for (; j + 1 < end; j += 2) {
                int s0 = esrc[j], s1 = esrc[j+1];
                float w0 = __expf(leaky(EL[s0*KH + k2] + er2));
                float w1 = __expf(leaky(EL[s1*KH + k2] + er2));
                z += w0 + w1;
                uint4 ha = *(const uint4*)(Hp + (size_t)s0*256 + lane*8);
                uint4 hb = *(const uint4*)(Hp + (size_t)s1*256 + lane*8);
                float2 a0 = __half22float2(*(__half2*)&ha.x);
                float2 a1 = __half22float2(*(__half2*)&ha.y);
                float2 a2 = __half22float2(*(__half2*)&ha.z);
                float2 a3 = __half22float2(*(__half2*)&ha.w);
                float2 b0 = __half22float2(*(__half2*)&hb.x);
                float2 b1 = __half22float2(*(__half2*)&hb.y);
                float2 b2 = __half22float2(*(__half2*)&hb.z);
                float2 b3 = __half22float2(*(__half2*)&hb.w);
                acc[0] += w0*a0.x + w1*b0.x; acc[1] += w0*a0.y + w1*b0.y;
                acc[2] += w0*a1.x + w1*b1.x; acc[3] += w0*a1.y + w1*b1.y;
                acc[4] += w0*a2.x + w1*b2.x; acc[5] += w0*a2.y + w1*b2.y;
                acc[6] += w0*a3.x + w1*b3.x; acc[7] += w0*a3.y + w1*b3.y;
            }
            if (j < end) {
                int s0 = esrc[j];
                float w0 = __expf(leaky(EL[s0*KH + k2] + er2));
                z += w0;
                uint4 ha = *(const uint4*)(Hp + (size_t)s0*256 + lane*8);
                float2 a0 = __half22float2(*(__half2*)&ha.x);
                float2 a1 = __half22float2(*(__half2*)&ha.y);
                float2 a2 = __half22float2(*(__half2*)&ha.z);
                float2 a3 = __half22float2(*(__half2*)&ha.w);
                acc[0] += w0*a0.x; acc[1] += w0*a0.y;
                acc[2] += w0*a1.x; acc[3] += w0*a1.y;
                acc[4] += w0*a2.x; acc[5] += w0*a2.y;
                acc[6] += w0*a3.x; acc[7] += w0*a3.y;
            }
            float rz = 1.0f / z;
            #pragma unroll
            for (int e = 0; e < 8; e++) acc[e] *= rz;
        }
        const float* ip = g_NR + (size_t)r*NC + (size_t)n*256 + lane*8;
        float4 ia = *(const float4*)ip;
        float4 ib = *(const float4*)(ip + 4);
        float* sp = &sh[nloc][q][lane*8];
        sp[0] = alpha*fmaxf(acc[0],0.f) + ia.x;
        sp[1] = alpha*fmaxf(acc[1],0.f) + ia.y;
        sp[2] = alpha*fmaxf(acc[2],0.f) + ia.z;
        sp[3] = alpha*fmaxf(acc[3],0.f) + ia.w;
        sp[4] = alpha*fmaxf(acc[4],0.f) + ib.x;
        sp[5] = alpha*fmaxf(acc[5],0.f) + ib.y;
        sp[6] = alpha*fmaxf(acc[6],0.f) + ib.z;
        sp[7] = alpha*fmaxf(acc[7],0.f) + ib.w;
    }
    __syncthreads();
    if (!valid) return;

    float h0[8], h1[8];
    {
        const float* p0 = &sh[nloc][0][lane*8];
        const float* p1 = &sh[nloc][1][lane*8];
        float4 a0 = *(const float4*)p0, a1 = *(const float4*)(p0+4);
        float4 b0 = *(const float4*)p1, b1 = *(const float4*)(p1+4);
        h0[0]=a0.x; h0[1]=a0.y; h0[2]=a0.z; h0[3]=a0.w;
        h0[4]=a1.x; h0[5]=a1.y; h0[6]=a1.z; h0[7]=a1.w;
        h1[0]=b0.x; h1[1]=b0.y; h1[2]=b0.z; h1[3]=b0.w;
        h1[4]=b1.x; h1[5]=b1.y; h1[6]=b1.z; h1[7]=b1.w;
    }
    int ro = q ? rel1 : rel0;
    const float* ra = rel_attn + ro*256 + lane*8;
    float s0 = 0.f, s1 = 0.f;
    #pragma unroll
    for (int j = 0; j < 8; j++) { s0 += h0[j]*ra[j]; s1 += h1[j]*ra[j]; }
    s0 += __shfl_xor_sync(0xffffffffu, s0, 1);
    s0 += __shfl_xor_sync(0xffffffffu, s0, 2);
    s1 += __shfl_xor_sync(0xffffffffu, s1, 1);
    s1 += __shfl_xor_sync(0xffffffffu, s1, 2);
    s0 = leaky(s0); s1 = leaky(s1);
    float mx = fmaxf(s0, s1);
    float w0 = __expf(s0 - mx), w1 = __expf(s1 - mx);
    float inv = 1.0f / (w0 + w1);
    w0 *= inv; w1 *= inv;
    float o[8];
    #pragma unroll
    for (int j = 0; j < 8; j++) o[j] = w0*h0[j] + w1*h1[j];
    float* op = out + (size_t)ro*NC + (size_t)n*256 + lane*8;
    *(float4*)op = make_float4(o[0],o[1],o[2],o[3]);
    *(float4*)(op+4) = make_float4(o[4],o[5],o[6],o[7]);
}

// ---------------- launch ----------------
extern "C" void kernel_launch(void* const* d_in, const int* in_sizes, int n_in,
                              void* d_out, int out_size) {
    const float* feats      = (const float*)d_in[0];
    const float* rel_feats  = (const float*)d_in[1];
    const int*   src_rates  = (const int*)d_in[2];
    const int*   dst_rates  = (const int*)d_in[3];
    const int*   src_clicks = (const int*)d_in[4];
    const int*   dst_clicks = (const int*)d_in[5];
    const float* W_node     = (const float*)d_in[6];
    const float* Wr         = (const float*)d_in[7];
    const float* Wres       = (const float*)d_in[8];
    const float* bres       = (const float*)d_in[9];
    const float* resw       = (const float*)d_in[10];
    const float* rel_attn   = (const float*)d_in[11];
    const float* Wupd       = (const float*)d_in[12];
    const float* bupd       = (const float*)d_in[13];
    float* out = (float*)d_out;

    const int* S0 = src_rates;  const int* S1 = dst_rates;
    const int* S2 = src_clicks; const int* S3 = dst_clicks;
    const int* D0 = dst_rates;  const int* D1 = src_rates;
    const int* D2 = dst_clicks; const int* D3 = src_clicks;

    static cudaStream_t s2 = nullptr;
    static cudaEvent_t evFork = nullptr, evJoin = nullptr;
    static int init_done = 0;
    if (!init_done) {
        cudaFuncSetAttribute(k_gemm_fp16, cudaFuncAttributeMaxDynamicSharedMemorySize, GSMEM_BYTES);
        cudaStreamCreateWithFlags(&s2, cudaStreamNonBlocking);
        cudaEventCreateWithFlags(&evFork, cudaEventDisableTiming);
        cudaEventCreateWithFlags(&evJoin, cudaEventDisableTiming);
        init_done = 1;
    }

    int setup_blocks = 9 + (4*NN + 511)/512;
    k_setup<<<setup_blocks, 512>>>(rel_feats, Wr, Wupd, bupd, resw, out);

    // fork: CSR chain on s2, GEMM path on the main stream
    cudaEventRecord(evFork, 0);
    cudaStreamWaitEvent(s2, evFork, 0);
    k_hist<<<dim3((EE + 255)/256, 4), 256, 0, s2>>>(D0, D1, D2, D3);
    k_scan<<<4, 1024, 0, s2>>>();
    k_scatter<<<dim3((EE + 255)/256, 4), 256, 0, s2>>>(S0,S1,S2,S3, D0,D1,D2,D3);
    cudaEventRecord(evJoin, s2);

    k_wsplit<<<2048, 256>>>(W_node, Wres);
    dim3 ggrid(512/GBN, (NN + GBM - 1)/GBM, 4);
    k_gemm_fp16<<<ggrid, 256, GSMEM_BYTES>>>(feats, bres);

    // join before the consumer
    cudaStreamWaitEvent(0, evJoin, 0);
    k_convcross<<<dim3((NN + 3)/4, 2), 256>>>(rel_attn, out);
}